// round 15
// baseline (speedup 1.0000x reference)
#include <cuda_runtime.h>
#include <math.h>

#define NW 1e-5f
#define CUTOFF_F 3.0f
#define SQRT2_F 1.41421356237309515f
#define INV_SQRT_PI_F 0.5641895835477563f
#define SQRT_LOG2E 1.2011224087864498f      // sqrt(log2(e))
#define THREE_S (3.0f * SQRT_LOG2E)         // 3 * sqrt(log2e)
#define NEG_LIM (-12.98325536919584f)       // -9 * log2(e)

#define PREP_TPB 256
#define TPB 128                // threads per block (main kernel), 4 warps
#define WARP_NTILE 64          // n-points per warp (NPT=2 within warp)
#define NTILE (4 * WARP_NTILE) // 256 n-points per block
#define CHUNK 128              // m-values per block
#define MAX_BM 65536

// Precomputed per-(b,m) params, stored m-SHUFFLED: {mu*c*s, c*s, k/s, 0}
__device__ float4 g_params[MAX_BM];

// Fused: precompute params for i < BM (store at shuffled position),
// zero output for BM <= i < BM+BN.
__global__ void __launch_bounds__(PREP_TPB)
prep_kernel(const float* __restrict__ res_fields,
            const float* __restrict__ width,
            const float* __restrict__ A_mean,
            const float* __restrict__ area,
            const float* __restrict__ sf,
            float* __restrict__ out,
            int B, int M, int N) {
    int i = blockIdx.x * PREP_TPB + threadIdx.x;
    int BM = B * M;
    if (i < BM) {
        int b = i / M;
        int m = i - b * M;

        float r0 = res_fields[i * 3 + 0];
        float r1 = res_fields[i * 3 + 1];
        float r2 = res_fields[i * 3 + 2];
        float t;
        if (r0 < r1) { t = r0; r0 = r1; r1 = t; }
        if (r1 < r2) { t = r1; r1 = r2; r2 = t; }
        if (r0 < r1) { t = r0; r0 = r1; r1 = t; }

        float w = width[i];
        w = (w > NW) ? w : w + NW;
        float invw = __fdividef(1.0f, w);
        float d13 = (r0 - r2) * invw;
        float d23 = (r1 - r2) * invw;
        float d12 = (r0 - r1) * invw;
        float add = (d13 * d13 + d23 * d23 + d12 * d12) * (1.0f / 9.0f);
        w = (w > 2.0f * NW) ? w : w + 2.0f * NW;

        float sw = (sf[b * N + 1] - sf[b * N]) * 0.5f;
        float ew = sqrtf(w * w * (1.0f + add) + sw * sw);
        ew = (ew < sw * 0.5f) ? ew : ew + sw * 0.5f;

        float mu = (r0 + r1 + r2) * (1.0f / 3.0f);
        float c  = SQRT2_F / ew;
        float A  = A_mean[i] * area[m];
        float k  = 2.0f * A * c * c * INV_SQRT_PI_F;

        // Shuffled store position: chunk composition becomes a stride sample
        // of the whole mu distribution -> uniform per-chunk survivor counts.
        int p;
        int nchunk = M / CHUNK;
        if (nchunk * CHUNK == M) {
            int q = m / nchunk;          // 0..CHUNK-1
            int r = m - q * nchunk;      // 0..nchunk-1
            p = r * CHUNK + q;
        } else {
            p = m;                        // fallback: identity
        }
        g_params[b * M + p] = make_float4(mu * c * SQRT_LOG2E, c * SQRT_LOG2E,
                                          k / SQRT_LOG2E, 0.0f);
    } else {
        int j = i - BM;
        if (j < B * N) out[j] = 0.0f;
    }
}

__global__ void __launch_bounds__(TPB)
spectra_main_kernel(const float* __restrict__ sf,
                    float* __restrict__ out,
                    int B, int M, int N) {
    // per-warp private compacted lists (no cross-warp sharing -> no barriers)
    __shared__ float4 sp[4][CHUNK];

    const int b  = blockIdx.z;
    const int mc = blockIdx.y;            // m-chunk index

    // Center-out remap: heavy (center-field) tiles first, light edge tiles last.
    const int nb = gridDim.x;
    const int x  = blockIdx.x;
    const int half = nb >> 1;
    int xx = (x & 1) ? (half - 1 - (x >> 1)) : (half + (x >> 1));
    if (xx < 0) xx = 0;
    if (xx >= nb) xx = nb - 1;

    const int lane = threadIdx.x & 31;
    const int warp = threadIdx.x >> 5;

    // Warp's n-subtile: 64 contiguous points, 2 per lane
    const int wbase = xx * NTILE + warp * WARP_NTILE;
    const int n0 = wbase + lane;
    const int n1 = n0 + 32;
    const int n0c = (n0 < N) ? n0 : (N - 1);
    const int n1c = (n1 < N) ? n1 : (N - 1);
    const float fn0 = -sf[b * N + n0c];
    const float fn1 = -sf[b * N + n1c];

    // Warp field range (uniform-address broadcast loads)
    int whi = wbase + WARP_NTILE - 1; if (whi >= N) whi = N - 1;
    int wlo = (wbase < N) ? wbase : (N - 1);
    const float flo = sf[b * N + wlo];
    const float fhi = sf[b * N + whi];
    const float bc = 0.5f * (flo + fhi);
    const float hr = 0.5f * (fhi - flo);

    // ---- Per-warp culling + compaction: 4 rounds of 32 m's, no barriers ----
    float4* mysp = sp[warp];
    const int mbase = mc * CHUNK;
    const size_t pbase = (size_t)b * M + mbase;
    int cnt = 0;
#pragma unroll
    for (int r = 0; r < 4; ++r) {
        int mm = r * 32 + lane;
        bool keep = false;
        float4 prm;
        if (mbase + mm < M) {
            prm = g_params[pbase + mm];           // coalesced LDG.128
            float t1   = fmaf(-bc, prm.y, prm.x);
            float lim2 = fmaf(hr,  prm.y, THREE_S);
            keep = (fabsf(t1) <= lim2);
        }
        unsigned bal = __ballot_sync(0xffffffffu, keep);
        int off = cnt + __popc(bal & ((1u << lane) - 1u));
        if (keep) mysp[off] = prm;
        cnt += __popc(bal);
    }
    __syncwarp();

    // ---- Main accumulation: 2 n-points per thread, fully predicated ----
    float acc0 = 0.0f, acc1 = 0.0f;
    const float lim = NEG_LIM;
#pragma unroll 4
    for (int j = 0; j < cnt; ++j) {
        float4 p = mysp[j];                          // broadcast LDS.128
        float argl0 = fmaf(fn0, p.y, p.x);
        float argl1 = fmaf(fn1, p.y, p.x);
        float tneg0 = argl0 * (-argl0);
        float tneg1 = argl1 * (-argl1);
        float e0, e1;
        asm("ex2.approx.ftz.f32 %0, %1;" : "=f"(e0) : "f"(tneg0));
        asm("ex2.approx.ftz.f32 %0, %1;" : "=f"(e1) : "f"(tneg1));
        float g0 = argl0 * e0;
        float g1 = argl1 * e1;
        asm("{\n\t"
            ".reg .pred q;\n\t"
            "setp.ge.f32 q, %1, %2;\n\t"
            "@q fma.rn.f32 %0, %3, %4, %0;\n\t"
            "}"
            : "+f"(acc0)
            : "f"(tneg0), "f"(lim), "f"(g0), "f"(p.z));
        asm("{\n\t"
            ".reg .pred q;\n\t"
            "setp.ge.f32 q, %1, %2;\n\t"
            "@q fma.rn.f32 %0, %3, %4, %0;\n\t"
            "}"
            : "+f"(acc1)
            : "f"(tneg1), "f"(lim), "f"(g1), "f"(p.z));
    }

    if (n0 < N) atomicAdd(&out[b * N + n0], acc0);
    if (n1 < N) atomicAdd(&out[b * N + n1], acc1);
}

extern "C" void kernel_launch(void* const* d_in, const int* in_sizes, int n_in,
                              void* d_out, int out_size) {
    const float* res_fields = (const float*)d_in[0];   // [B, M, 3]
    const float* width      = (const float*)d_in[1];   // [B, M]
    const float* A_mean     = (const float*)d_in[2];   // [B, M]
    const float* area       = (const float*)d_in[3];   // [M]
    const float* sf         = (const float*)d_in[4];   // [B, N]
    float* out = (float*)d_out;                        // [B, N]

    int M = in_sizes[3];
    int B = in_sizes[1] / M;
    int N = in_sizes[4] / B;

    int BM = B * M;
    int BN = B * N;
    int num_chunks = (M + CHUNK - 1) / CHUNK;
    int nblocks = (N + NTILE - 1) / NTILE;

    int prep_items = BM + BN;
    prep_kernel<<<(prep_items + PREP_TPB - 1) / PREP_TPB, PREP_TPB>>>(
        res_fields, width, A_mean, area, sf, out, B, M, N);

    dim3 grid(nblocks, num_chunks, B);
    spectra_main_kernel<<<grid, TPB>>>(sf, out, B, M, N);
}

// round 16
// speedup vs baseline: 1.1212x; 1.1212x over previous
#include <cuda_runtime.h>
#include <math.h>

#define NW 1e-5f
#define CUTOFF_F 3.0f
#define SQRT2_F 1.41421356237309515f
#define INV_SQRT_PI_F 0.5641895835477563f
#define SQRT_LOG2E 1.2011224087864498f      // sqrt(log2(e))
#define THREE_S (3.0f * SQRT_LOG2E)         // 3 * sqrt(log2e)
#define NEG_LIM (-12.98325536919584f)       // -9 * log2(e)

#define PREP_TPB 256
#define TPB 128                // threads per block (main kernel), 4 warps
#define WARP_NTILE 64          // n-points per warp (NPT=2 within warp)
#define NTILE (4 * WARP_NTILE) // 256 n-points per block
#define CHUNK 128              // m-values per block
#define PAD 8                  // pad compacted count to multiple of 8
#define SP_CAP (CHUNK + PAD)   // room for padding
#define MAX_BM 65536

// Precomputed per-(b,m) params: {mu*c*s, c*s, k/s, 0}
__device__ float4 g_params[MAX_BM];

// Fused: precompute params for i < BM, zero output for BM <= i < BM+BN.
__global__ void __launch_bounds__(PREP_TPB)
prep_kernel(const float* __restrict__ res_fields,
            const float* __restrict__ width,
            const float* __restrict__ A_mean,
            const float* __restrict__ area,
            const float* __restrict__ sf,
            float* __restrict__ out,
            int B, int M, int N) {
    int i = blockIdx.x * PREP_TPB + threadIdx.x;
    int BM = B * M;
    if (i < BM) {
        int b = i / M;
        int m = i - b * M;

        float r0 = res_fields[i * 3 + 0];
        float r1 = res_fields[i * 3 + 1];
        float r2 = res_fields[i * 3 + 2];
        float t;
        if (r0 < r1) { t = r0; r0 = r1; r1 = t; }
        if (r1 < r2) { t = r1; r1 = r2; r2 = t; }
        if (r0 < r1) { t = r0; r0 = r1; r1 = t; }

        float w = width[i];
        w = (w > NW) ? w : w + NW;
        float invw = __fdividef(1.0f, w);
        float d13 = (r0 - r2) * invw;
        float d23 = (r1 - r2) * invw;
        float d12 = (r0 - r1) * invw;
        float add = (d13 * d13 + d23 * d23 + d12 * d12) * (1.0f / 9.0f);
        w = (w > 2.0f * NW) ? w : w + 2.0f * NW;

        float sw = (sf[b * N + 1] - sf[b * N]) * 0.5f;
        float ew = sqrtf(w * w * (1.0f + add) + sw * sw);
        ew = (ew < sw * 0.5f) ? ew : ew + sw * 0.5f;

        float mu = (r0 + r1 + r2) * (1.0f / 3.0f);
        float c  = SQRT2_F / ew;
        float A  = A_mean[i] * area[m];
        float k  = 2.0f * A * c * c * INV_SQRT_PI_F;

        g_params[i] = make_float4(mu * c * SQRT_LOG2E, c * SQRT_LOG2E,
                                  k / SQRT_LOG2E, 0.0f);
    } else {
        int j = i - BM;
        if (j < B * N) out[j] = 0.0f;
    }
}

__global__ void __launch_bounds__(TPB)
spectra_main_kernel(const float* __restrict__ sf,
                    float* __restrict__ out,
                    int B, int M, int N, int m_full) {
    // per-warp private compacted lists (no cross-warp sharing -> no barriers)
    __shared__ float4 sp[4][SP_CAP];

    const int b  = blockIdx.z;
    const int mc = blockIdx.y;            // m-chunk index

    // Center-out remap: heavy (center-field) tiles first, light edge tiles last.
    const int nb = gridDim.x;
    const int x  = blockIdx.x;
    const int half = nb >> 1;
    int xx = (x & 1) ? (half - 1 - (x >> 1)) : (half + (x >> 1));
    if (xx < 0) xx = 0;
    if (xx >= nb) xx = nb - 1;

    const int lane = threadIdx.x & 31;
    const int warp = threadIdx.x >> 5;

    // Warp's n-subtile: 64 contiguous points, 2 per lane
    const int wbase = xx * NTILE + warp * WARP_NTILE;
    const int n0 = wbase + lane;
    const int n1 = n0 + 32;
    const int n0c = (n0 < N) ? n0 : (N - 1);
    const int n1c = (n1 < N) ? n1 : (N - 1);
    const float fn0 = -sf[b * N + n0c];
    const float fn1 = -sf[b * N + n1c];

    // Warp field range (uniform-address broadcast loads)
    int whi = wbase + WARP_NTILE - 1; if (whi >= N) whi = N - 1;
    int wlo = (wbase < N) ? wbase : (N - 1);
    const float flo = sf[b * N + wlo];
    const float fhi = sf[b * N + whi];
    const float bc = 0.5f * (flo + fhi);
    const float hr = 0.5f * (fhi - flo);

    // ---- Per-warp culling: front-batched LDGs (MLP=4), then ballot/compact ----
    float4* mysp = sp[warp];
    const int mbase = mc * CHUNK;
    const size_t pbase = (size_t)b * M + mbase;

    float4 prm0, prm1, prm2, prm3;
    if (m_full) {
        prm0 = g_params[pbase + 0 * 32 + lane];
        prm1 = g_params[pbase + 1 * 32 + lane];
        prm2 = g_params[pbase + 2 * 32 + lane];
        prm3 = g_params[pbase + 3 * 32 + lane];
    } else {
        float4 z = make_float4(0.0f, 0.0f, 0.0f, 0.0f);
        prm0 = (mbase + 0 * 32 + lane < M) ? g_params[pbase + 0 * 32 + lane] : z;
        prm1 = (mbase + 1 * 32 + lane < M) ? g_params[pbase + 1 * 32 + lane] : z;
        prm2 = (mbase + 2 * 32 + lane < M) ? g_params[pbase + 2 * 32 + lane] : z;
        prm3 = (mbase + 3 * 32 + lane < M) ? g_params[pbase + 3 * 32 + lane] : z;
    }

    int cnt = 0;
    {
        float4 prms[4] = {prm0, prm1, prm2, prm3};
#pragma unroll
        for (int r = 0; r < 4; ++r) {
            float4 prm = prms[r];
            float t1   = fmaf(-bc, prm.y, prm.x);
            float lim2 = fmaf(hr,  prm.y, THREE_S);
            // zero-filled entries: t1=0 <= lim2=THREE_S -> keep, but k=0 -> no effect
            bool keep = (fabsf(t1) <= lim2) && (prm.z != 0.0f || prm.y != 0.0f);
            unsigned bal = __ballot_sync(0xffffffffu, keep);
            int off = cnt + __popc(bal & ((1u << lane) - 1u));
            if (keep) mysp[off] = prm;
            cnt += __popc(bal);
        }
    }
    // Pad to multiple of 8 with zero entries (contribute exactly 0)
    {
        int padded = (cnt + 7) & ~7;
        if (lane < padded - cnt)
            mysp[cnt + lane] = make_float4(0.0f, 0.0f, 0.0f, 0.0f);
        cnt = padded;
    }
    __syncwarp();

    // ---- Main accumulation: 2 n-points per thread, fully predicated, unroll 8 ----
    float acc0 = 0.0f, acc1 = 0.0f;
    const float lim = NEG_LIM;
#pragma unroll 8
    for (int j = 0; j < cnt; ++j) {
        float4 p = mysp[j];                          // broadcast LDS.128
        float argl0 = fmaf(fn0, p.y, p.x);
        float argl1 = fmaf(fn1, p.y, p.x);
        float tneg0 = argl0 * (-argl0);
        float tneg1 = argl1 * (-argl1);
        float e0, e1;
        asm("ex2.approx.ftz.f32 %0, %1;" : "=f"(e0) : "f"(tneg0));
        asm("ex2.approx.ftz.f32 %0, %1;" : "=f"(e1) : "f"(tneg1));
        float g0 = argl0 * e0;
        float g1 = argl1 * e1;
        asm("{\n\t"
            ".reg .pred q;\n\t"
            "setp.ge.f32 q, %1, %2;\n\t"
            "@q fma.rn.f32 %0, %3, %4, %0;\n\t"
            "}"
            : "+f"(acc0)
            : "f"(tneg0), "f"(lim), "f"(g0), "f"(p.z));
        asm("{\n\t"
            ".reg .pred q;\n\t"
            "setp.ge.f32 q, %1, %2;\n\t"
            "@q fma.rn.f32 %0, %3, %4, %0;\n\t"
            "}"
            : "+f"(acc1)
            : "f"(tneg1), "f"(lim), "f"(g1), "f"(p.z));
    }

    if (n0 < N) atomicAdd(&out[b * N + n0], acc0);
    if (n1 < N) atomicAdd(&out[b * N + n1], acc1);
}

extern "C" void kernel_launch(void* const* d_in, const int* in_sizes, int n_in,
                              void* d_out, int out_size) {
    const float* res_fields = (const float*)d_in[0];   // [B, M, 3]
    const float* width      = (const float*)d_in[1];   // [B, M]
    const float* A_mean     = (const float*)d_in[2];   // [B, M]
    const float* area       = (const float*)d_in[3];   // [M]
    const float* sf         = (const float*)d_in[4];   // [B, N]
    float* out = (float*)d_out;                        // [B, N]

    int M = in_sizes[3];
    int B = in_sizes[1] / M;
    int N = in_sizes[4] / B;

    int BM = B * M;
    int BN = B * N;
    int num_chunks = (M + CHUNK - 1) / CHUNK;
    int nblocks = (N + NTILE - 1) / NTILE;
    int m_full = (num_chunks * CHUNK == M) ? 1 : 0;

    int prep_items = BM + BN;
    prep_kernel<<<(prep_items + PREP_TPB - 1) / PREP_TPB, PREP_TPB>>>(
        res_fields, width, A_mean, area, sf, out, B, M, N);

    dim3 grid(nblocks, num_chunks, B);
    spectra_main_kernel<<<grid, TPB>>>(sf, out, B, M, N, m_full);
}

// round 17
// speedup vs baseline: 1.1233x; 1.0019x over previous
#include <cuda_runtime.h>
#include <math.h>

#define NW 1e-5f
#define CUTOFF_F 3.0f
#define SQRT2_F 1.41421356237309515f
#define INV_SQRT_PI_F 0.5641895835477563f
#define SQRT_LOG2E 1.2011224087864498f      // sqrt(log2(e))
#define THREE_S (3.0f * SQRT_LOG2E)         // 3 * sqrt(log2e)
#define NEG_LIM (-12.98325536919584f)       // -9 * log2(e)

#define PREP_TPB 256
#define TPB 128                // threads per block (main kernel), 4 warps
#define WARP_NTILE 64          // n-points per warp (NPT=2 within warp)
#define NTILE (4 * WARP_NTILE) // 256 n-points per block
#define CHUNK 64               // m-values per block -> 4096 CTAs (~2 waves)
#define PAD 8                  // pad compacted count to multiple of 8
#define SP_CAP (CHUNK + PAD)
#define MAX_BM 65536

// Precomputed per-(b,m) params: {mu*c*s, c*s, k/s, 0}
__device__ float4 g_params[MAX_BM];

// Fused: precompute params for i < BM, zero output for BM <= i < BM+BN.
__global__ void __launch_bounds__(PREP_TPB)
prep_kernel(const float* __restrict__ res_fields,
            const float* __restrict__ width,
            const float* __restrict__ A_mean,
            const float* __restrict__ area,
            const float* __restrict__ sf,
            float* __restrict__ out,
            int B, int M, int N) {
    int i = blockIdx.x * PREP_TPB + threadIdx.x;
    int BM = B * M;
    if (i < BM) {
        int b = i / M;
        int m = i - b * M;

        float r0 = res_fields[i * 3 + 0];
        float r1 = res_fields[i * 3 + 1];
        float r2 = res_fields[i * 3 + 2];
        float t;
        if (r0 < r1) { t = r0; r0 = r1; r1 = t; }
        if (r1 < r2) { t = r1; r1 = r2; r2 = t; }
        if (r0 < r1) { t = r0; r0 = r1; r1 = t; }

        float w = width[i];
        w = (w > NW) ? w : w + NW;
        float invw = __fdividef(1.0f, w);
        float d13 = (r0 - r2) * invw;
        float d23 = (r1 - r2) * invw;
        float d12 = (r0 - r1) * invw;
        float add = (d13 * d13 + d23 * d23 + d12 * d12) * (1.0f / 9.0f);
        w = (w > 2.0f * NW) ? w : w + 2.0f * NW;

        float sw = (sf[b * N + 1] - sf[b * N]) * 0.5f;
        float ew = sqrtf(w * w * (1.0f + add) + sw * sw);
        ew = (ew < sw * 0.5f) ? ew : ew + sw * 0.5f;

        float mu = (r0 + r1 + r2) * (1.0f / 3.0f);
        float c  = SQRT2_F / ew;
        float A  = A_mean[i] * area[m];
        float k  = 2.0f * A * c * c * INV_SQRT_PI_F;

        g_params[i] = make_float4(mu * c * SQRT_LOG2E, c * SQRT_LOG2E,
                                  k / SQRT_LOG2E, 0.0f);
    } else {
        int j = i - BM;
        if (j < B * N) out[j] = 0.0f;
    }
}

__global__ void __launch_bounds__(TPB)
spectra_main_kernel(const float* __restrict__ sf,
                    float* __restrict__ out,
                    int B, int M, int N, int m_full) {
    // per-warp private compacted lists (no cross-warp sharing -> no barriers)
    __shared__ float4 sp[4][SP_CAP];

    const int b  = blockIdx.z;
    const int mc = blockIdx.y;            // m-chunk index
    const int xx = blockIdx.x;            // n-tile index (no remap; multi-wave)

    const int lane = threadIdx.x & 31;
    const int warp = threadIdx.x >> 5;

    // Warp's n-subtile: 64 contiguous points, 2 per lane
    const int wbase = xx * NTILE + warp * WARP_NTILE;
    const int n0 = wbase + lane;
    const int n1 = n0 + 32;
    const int n0c = (n0 < N) ? n0 : (N - 1);
    const int n1c = (n1 < N) ? n1 : (N - 1);
    const float fn0 = -sf[b * N + n0c];
    const float fn1 = -sf[b * N + n1c];

    // Warp field range (uniform-address broadcast loads)
    int whi = wbase + WARP_NTILE - 1; if (whi >= N) whi = N - 1;
    int wlo = (wbase < N) ? wbase : (N - 1);
    const float flo = sf[b * N + wlo];
    const float fhi = sf[b * N + whi];
    const float bc = 0.5f * (flo + fhi);
    const float hr = 0.5f * (fhi - flo);

    // ---- Per-warp culling: front-batched LDGs (MLP=2), then ballot/compact ----
    float4* mysp = sp[warp];
    const int mbase = mc * CHUNK;
    const size_t pbase = (size_t)b * M + mbase;

    float4 prm0, prm1;
    if (m_full) {
        prm0 = g_params[pbase + 0 * 32 + lane];
        prm1 = g_params[pbase + 1 * 32 + lane];
    } else {
        float4 z = make_float4(0.0f, 0.0f, 0.0f, 0.0f);
        prm0 = (mbase + 0 * 32 + lane < M) ? g_params[pbase + 0 * 32 + lane] : z;
        prm1 = (mbase + 1 * 32 + lane < M) ? g_params[pbase + 1 * 32 + lane] : z;
    }

    int cnt = 0;
    {
        float4 prms[2] = {prm0, prm1};
#pragma unroll
        for (int r = 0; r < 2; ++r) {
            float4 prm = prms[r];
            float t1   = fmaf(-bc, prm.y, prm.x);
            float lim2 = fmaf(hr,  prm.y, THREE_S);
            bool keep = (fabsf(t1) <= lim2) && (prm.z != 0.0f || prm.y != 0.0f);
            unsigned bal = __ballot_sync(0xffffffffu, keep);
            int off = cnt + __popc(bal & ((1u << lane) - 1u));
            if (keep) mysp[off] = prm;
            cnt += __popc(bal);
        }
    }
    // Pad to multiple of 8 with zero entries (contribute exactly 0)
    {
        int padded = (cnt + 7) & ~7;
        if (lane < padded - cnt)
            mysp[cnt + lane] = make_float4(0.0f, 0.0f, 0.0f, 0.0f);
        cnt = padded;
    }
    __syncwarp();

    // ---- Main accumulation: 2 n-points per thread, fully predicated, unroll 8 ----
    float acc0 = 0.0f, acc1 = 0.0f;
    const float lim = NEG_LIM;
#pragma unroll 8
    for (int j = 0; j < cnt; ++j) {
        float4 p = mysp[j];                          // broadcast LDS.128
        float argl0 = fmaf(fn0, p.y, p.x);
        float argl1 = fmaf(fn1, p.y, p.x);
        float tneg0 = argl0 * (-argl0);
        float tneg1 = argl1 * (-argl1);
        float e0, e1;
        asm("ex2.approx.ftz.f32 %0, %1;" : "=f"(e0) : "f"(tneg0));
        asm("ex2.approx.ftz.f32 %0, %1;" : "=f"(e1) : "f"(tneg1));
        float g0 = argl0 * e0;
        float g1 = argl1 * e1;
        asm("{\n\t"
            ".reg .pred q;\n\t"
            "setp.ge.f32 q, %1, %2;\n\t"
            "@q fma.rn.f32 %0, %3, %4, %0;\n\t"
            "}"
            : "+f"(acc0)
            : "f"(tneg0), "f"(lim), "f"(g0), "f"(p.z));
        asm("{\n\t"
            ".reg .pred q;\n\t"
            "setp.ge.f32 q, %1, %2;\n\t"
            "@q fma.rn.f32 %0, %3, %4, %0;\n\t"
            "}"
            : "+f"(acc1)
            : "f"(tneg1), "f"(lim), "f"(g1), "f"(p.z));
    }

    if (n0 < N) atomicAdd(&out[b * N + n0], acc0);
    if (n1 < N) atomicAdd(&out[b * N + n1], acc1);
}

extern "C" void kernel_launch(void* const* d_in, const int* in_sizes, int n_in,
                              void* d_out, int out_size) {
    const float* res_fields = (const float*)d_in[0];   // [B, M, 3]
    const float* width      = (const float*)d_in[1];   // [B, M]
    const float* A_mean     = (const float*)d_in[2];   // [B, M]
    const float* area       = (const float*)d_in[3];   // [M]
    const float* sf         = (const float*)d_in[4];   // [B, N]
    float* out = (float*)d_out;                        // [B, N]

    int M = in_sizes[3];
    int B = in_sizes[1] / M;
    int N = in_sizes[4] / B;

    int BM = B * M;
    int BN = B * N;
    int num_chunks = (M + CHUNK - 1) / CHUNK;
    int nblocks = (N + NTILE - 1) / NTILE;
    int m_full = (num_chunks * CHUNK == M) ? 1 : 0;

    int prep_items = BM + BN;
    prep_kernel<<<(prep_items + PREP_TPB - 1) / PREP_TPB, PREP_TPB>>>(
        res_fields, width, A_mean, area, sf, out, B, M, N);

    dim3 grid(nblocks, num_chunks, B);
    spectra_main_kernel<<<grid, TPB>>>(sf, out, B, M, N, m_full);
}